// round 13
// baseline (speedup 1.0000x reference)
#include <cuda_runtime.h>
#include <math.h>
#include <float.h>

#define BZ 16
#define CIN 3
#define FF 64
#define NNODE 307
#define TT 24
#define KT 3
#define BT (BZ*TT)               /* 384 */
#define BTN (BT*NNODE)           /* 117888 */
#define ELEMS (BZ*FF*NNODE*TT)   /* 7544832 */
#define PERB (FF*NNODE*TT)       /* 471552 */
#define S_SIZE ((long long)BT*NNODE*NNODE)  /* 36191616 */

typedef unsigned long long ull;
__device__ __forceinline__ ull pk2(float lo, float hi) {
    ull r; asm("mov.b64 %0, {%1,%2};" : "=l"(r) : "f"(lo), "f"(hi)); return r;
}
__device__ __forceinline__ ull fma2(ull a, ull b, ull c) {
    ull d; asm("fma.rn.f32x2 %0, %1, %2, %3;" : "=l"(d) : "l"(a), "l"(b), "l"(c)); return d;
}
__device__ __forceinline__ float2 upk2(ull v) {
    float2 r; asm("mov.b64 {%0,%1}, %2;" : "=f"(r.x), "=f"(r.y) : "l"(v)); return r;
}
__device__ __forceinline__ unsigned cvt_tf32(float f) {
    unsigned u; asm("cvt.rna.tf32.f32 %0, %1;" : "=r"(u) : "f"(f)); return u;
}

// ---------------- scratch ----------------
__device__ float g_x1a[ELEMS];    // lrelu(temporal conv) [b,n,t,c]
__device__ float g_h1[ELEMS];     // h for GAT1 [b,t,n,f]
__device__ float g_h2[ELEMS];     // h for GAT2 [b,t,n,f]
__device__ float g_o1[ELEMS];     // GAT1 out [b,t,n,f]
__device__ float g_o2[ELEMS];     // GAT2 out [b,t,n,f]
__device__ float g_x1g[ELEMS];    // sigmoid(gate)*lrelu(filt) [b,c,n,t]
__device__ float g_y[ELEMS];      // pre-LN [b,c,n,t]
__device__ float g_es1[BTN], g_ed1[BTN], g_es2[BTN], g_ed2[BTN];
__device__ float g_wa[4*FF];
__device__ float g_f1[BTN];           // [b,t,n]
__device__ float g_f2[BZ*FF*TT];      // [b,c,t]
__device__ float g_gm[BZ*NNODE*TT];   // [b,n,q]
__device__ float g_lg[BZ*TT*TT];      // [b,t,q]
__device__ double g_part[16*80*2];
__device__ float g_mu[BZ], g_rstd[BZ];

__device__ __forceinline__ float lrelu(float v, float s) { return v > 0.f ? v : s * v; }

// ---------------- temporal conv (1,3), pad (0,1), lrelu(0.01) ------------
__global__ void k_tconv(const float* __restrict__ x, const float* __restrict__ w,
                        const float* __restrict__ bias) {
    int idx = blockIdx.x * blockDim.x + threadIdx.x;  // [b,n,t,o], o fastest
    if (idx >= ELEMS) return;
    int o = idx % FF;
    int t = (idx / FF) % TT;
    int n = (idx / (FF * TT)) % NNODE;
    int b = idx / (FF * TT * NNODE);
    float s = bias[o];
#pragma unroll
    for (int c = 0; c < CIN; c++) {
#pragma unroll
        for (int k = 0; k < KT; k++) {
            int tt = t - 1 + k;
            if (tt >= 0 && tt < TT)
                s += x[((size_t)(b * CIN + c) * NNODE + n) * TT + tt] * w[(o * CIN + c) * KT + k];
        }
    }
    g_x1a[idx] = lrelu(s, 0.01f);
}

// ---------------- wa[c] = sum_f W[c,f]*a[f] ------------------------------
__global__ void k_wa(const float* __restrict__ W1, const float* __restrict__ a1s,
                     const float* __restrict__ a1d, const float* __restrict__ W2,
                     const float* __restrict__ a2s, const float* __restrict__ a2d) {
    int c = threadIdx.x;
    float s0 = 0.f, s1 = 0.f, s2 = 0.f, s3 = 0.f;
    for (int f = 0; f < FF; f++) {
        float w1 = W1[c * FF + f], w2 = W2[c * FF + f];
        s0 += w1 * a1s[f]; s1 += w1 * a1d[f];
        s2 += w2 * a2s[f]; s3 += w2 * a2d[f];
    }
    g_wa[c] = s0; g_wa[FF + c] = s1; g_wa[2 * FF + c] = s2; g_wa[3 * FF + c] = s3;
}

// ---------------- es/ed = x1a . wa  (warp per row) -----------------------
__global__ void k_esed() {
    int row = blockIdx.x * 8 + (threadIdx.x >> 5);
    if (row >= BTN) return;
    int lane = threadIdx.x & 31;
    int n = row % NNODE;
    int bt = row / NNODE;
    int b = bt / TT, t = bt % TT;
    const float* xr = g_x1a + ((size_t)(b * NNODE + n) * TT + t) * FF;
    float x0 = xr[lane], x1 = xr[lane + 32];
    float s0 = x0 * g_wa[lane]        + x1 * g_wa[lane + 32];
    float s1 = x0 * g_wa[FF + lane]   + x1 * g_wa[FF + lane + 32];
    float s2 = x0 * g_wa[2*FF + lane] + x1 * g_wa[2*FF + lane + 32];
    float s3 = x0 * g_wa[3*FF + lane] + x1 * g_wa[3*FF + lane + 32];
#pragma unroll
    for (int o = 16; o > 0; o >>= 1) {
        s0 += __shfl_xor_sync(0xffffffffu, s0, o);
        s1 += __shfl_xor_sync(0xffffffffu, s1, o);
        s2 += __shfl_xor_sync(0xffffffffu, s2, o);
        s3 += __shfl_xor_sync(0xffffffffu, s3, o);
    }
    if (lane == 0) { g_es1[row] = s0; g_ed1[row] = s1; g_es2[row] = s2; g_ed2[row] = s3; }
}

// ---------------- h1|h2 = x1a @ [W1|W2]  (tf32 MMA, N=128) ----------------
// grid (5, BT), block 128. dyn smem: As[64][68] + Ws[64][136] (tf32 bits)
extern __shared__ unsigned dyn_smem[];
__global__ void k_hmma(const float* __restrict__ W1, const float* __restrict__ W2) {
    unsigned (*As)[68] = (unsigned(*)[68])dyn_smem;
    unsigned (*Ws)[136] = (unsigned(*)[136])(dyn_smem + 64 * 68);
    int bt = blockIdx.y;
    int b = bt / TT, t = bt % TT;
    int m0 = blockIdx.x * 64;
    int tid = threadIdx.x, wid = tid >> 5, lane = tid & 31;
    int g = lane >> 2, tg = lane & 3;
    int wm = wid >> 1, wn = wid & 1;

    for (int i = tid; i < 4096; i += 128) {
        int r = i >> 6, c = i & 63;
        int n = m0 + r;
        float v = (n < NNODE) ? g_x1a[((size_t)(b * NNODE + n) * TT + t) * FF + c] : 0.f;
        As[r][c] = cvt_tf32(v);
    }
    for (int i = tid; i < 8192; i += 128) {
        int k = i >> 7, f = i & 127;
        float v = (f < 64) ? W1[k * FF + f] : W2[k * FF + (f - 64)];
        Ws[k][f] = cvt_tf32(v);
    }
    __syncthreads();

    float acc[2][8][4];
#pragma unroll
    for (int mt = 0; mt < 2; mt++)
#pragma unroll
        for (int nt = 0; nt < 8; nt++)
#pragma unroll
            for (int r = 0; r < 4; r++) acc[mt][nt][r] = 0.f;

#pragma unroll
    for (int k8 = 0; k8 < 64; k8 += 8) {
        unsigned a[2][4], bfr[8][2];
#pragma unroll
        for (int mt = 0; mt < 2; mt++) {
            int rb = wm * 32 + mt * 16 + g;
            a[mt][0] = As[rb][k8 + tg];
            a[mt][1] = As[rb + 8][k8 + tg];
            a[mt][2] = As[rb][k8 + tg + 4];
            a[mt][3] = As[rb + 8][k8 + tg + 4];
        }
#pragma unroll
        for (int nt = 0; nt < 8; nt++) {
            int cb = wn * 64 + nt * 8 + g;
            bfr[nt][0] = Ws[k8 + tg][cb];
            bfr[nt][1] = Ws[k8 + tg + 4][cb];
        }
#pragma unroll
        for (int mt = 0; mt < 2; mt++)
#pragma unroll
            for (int nt = 0; nt < 8; nt++)
                asm volatile(
                    "mma.sync.aligned.m16n8k8.row.col.f32.tf32.tf32.f32 "
                    "{%0,%1,%2,%3}, {%4,%5,%6,%7}, {%8,%9}, {%0,%1,%2,%3};"
                    : "+f"(acc[mt][nt][0]), "+f"(acc[mt][nt][1]),
                      "+f"(acc[mt][nt][2]), "+f"(acc[mt][nt][3])
                    : "r"(a[mt][0]), "r"(a[mt][1]), "r"(a[mt][2]), "r"(a[mt][3]),
                      "r"(bfr[nt][0]), "r"(bfr[nt][1]));
    }
#pragma unroll
    for (int mt = 0; mt < 2; mt++) {
        int l0 = wm * 32 + mt * 16 + g;
        int n0v = m0 + l0, n1v = n0v + 8;
#pragma unroll
        for (int nt = 0; nt < 8; nt++) {
            int c = wn * 64 + nt * 8 + 2 * tg;
            float* dst = (c < 64) ? g_h1 : g_h2;
            int cc = c & 63;
            if (n0v < NNODE)
                *(float2*)&dst[((size_t)bt * NNODE + n0v) * FF + cc] = make_float2(acc[mt][nt][0], acc[mt][nt][1]);
            if (n1v < NNODE)
                *(float2*)&dst[((size_t)bt * NNODE + n1v) * FF + cc] = make_float2(acc[mt][nt][2], acc[mt][nt][3]);
        }
    }
}

// ------ fused softmax + tf32 aggregation: out = softmax(e) @ h -----------
// grid (5, BT, 2), block 128 (4 warps). BM=BN=64, BK=32.
// A tile is COMPUTED (exp of masked lrelu(es+ed)); normalization deferred
// to the accumulator scale (linearity). Head 0 also writes normalized Sc.
__global__ void k_fagg(const float* __restrict__ adj, float* __restrict__ Sc) {
    __shared__ float As[64][36];       // fp32 exp values
    __shared__ unsigned Bs[32][68];
    __shared__ float ess[64];
    __shared__ float rinv[64];
    int bt = blockIdx.y;
    int head = blockIdx.z;
    int m0 = blockIdx.x * 64;
    const float* es = (head ? g_es2 : g_es1) + (size_t)bt * NNODE;
    const float* ed = (head ? g_ed2 : g_ed1) + (size_t)bt * NNODE;
    const float* B = (head ? g_h2 : g_h1) + (size_t)bt * NNODE * FF;
    float* outp = (head ? g_o2 : g_o1) + (size_t)bt * NNODE * FF;
    int tid = threadIdx.x, wid = tid >> 5, lane = tid & 31;
    int g = lane >> 2, tg = lane & 3;
    int wm = wid >> 1, wn = wid & 1;

    if (tid < 64) {
        int gr = m0 + tid;
        ess[tid] = (gr < NNODE) ? es[gr] : 0.f;
    }
    __syncthreads();

    float acc[2][4][4];
#pragma unroll
    for (int mt = 0; mt < 2; mt++)
#pragma unroll
        for (int nt = 0; nt < 4; nt++)
#pragma unroll
            for (int r = 0; r < 4; r++) acc[mt][nt][r] = 0.f;

    float part[16];
#pragma unroll
    for (int s = 0; s < 16; s++) part[s] = 0.f;
    int c = lane;          // this thread's fixed column within the chunk
    int rb0 = wid;         // row base: r = wid + 4*s

    for (int k0 = 0; k0 < 320; k0 += 32) {
        int gc = k0 + c;
        float edc = (gc < NNODE) ? ed[gc] : 0.f;
        // A tile: compute exp values
#pragma unroll
        for (int s = 0; s < 16; s++) {
            int r = rb0 + 4 * s;
            int gr = m0 + r;
            float val = 0.f;
            if (gr < NNODE && gc < NNODE) {
                float a = adj[(size_t)gr * NNODE + gc];
                if (a > 0.f) {
                    float v = ess[r] + edc;
                    v = v > 0.f ? v : 0.3f * v;
                    val = __expf(v);
                }
            }
            As[r][c] = val;
            part[s] += val;
        }
        // B tile 32x64 (scalar coalesced + cvt, as proven in R8)
        for (int i = tid; i < 2048; i += 128) {
            int r = i >> 6, cc = i & 63;
            int gk = k0 + r;
            float v = (gk < NNODE) ? B[(size_t)gk * FF + cc] : 0.f;
            Bs[r][cc] = cvt_tf32(v);
        }
        __syncthreads();
#pragma unroll
        for (int k8 = 0; k8 < 32; k8 += 8) {
            unsigned a[2][4], b[4][2];
#pragma unroll
            for (int mt = 0; mt < 2; mt++) {
                int rb = wm * 32 + mt * 16 + g;
                a[mt][0] = cvt_tf32(As[rb][k8 + tg]);
                a[mt][1] = cvt_tf32(As[rb + 8][k8 + tg]);
                a[mt][2] = cvt_tf32(As[rb][k8 + tg + 4]);
                a[mt][3] = cvt_tf32(As[rb + 8][k8 + tg + 4]);
            }
#pragma unroll
            for (int nt = 0; nt < 4; nt++) {
                int cb = wn * 32 + nt * 8 + g;
                b[nt][0] = Bs[k8 + tg][cb];
                b[nt][1] = Bs[k8 + tg + 4][cb];
            }
#pragma unroll
            for (int mt = 0; mt < 2; mt++)
#pragma unroll
                for (int nt = 0; nt < 4; nt++)
                    asm volatile(
                        "mma.sync.aligned.m16n8k8.row.col.f32.tf32.tf32.f32 "
                        "{%0,%1,%2,%3}, {%4,%5,%6,%7}, {%8,%9}, {%0,%1,%2,%3};"
                        : "+f"(acc[mt][nt][0]), "+f"(acc[mt][nt][1]),
                          "+f"(acc[mt][nt][2]), "+f"(acc[mt][nt][3])
                        : "r"(a[mt][0]), "r"(a[mt][1]), "r"(a[mt][2]), "r"(a[mt][3]),
                          "r"(b[nt][0]), "r"(b[nt][1]));
        }
        __syncthreads();
    }

    // row-sum reduction: park column partials in As, reduce per row
#pragma unroll
    for (int s = 0; s < 16; s++) As[rb0 + 4 * s][c] = part[s];
    __syncthreads();
    if (tid < 64) {
        float ssum = 0.f;
#pragma unroll 8
        for (int j = 0; j < 32; j++) ssum += As[tid][j];
        rinv[tid] = (ssum > 0.f) ? 1.f / ssum : 0.f;
    }
    __syncthreads();

    // scaled store
#pragma unroll
    for (int mt = 0; mt < 2; mt++) {
        int l0 = wm * 32 + mt * 16 + g;
        float i0 = rinv[l0], i1 = rinv[l0 + 8];
        int r0 = m0 + l0, r1 = r0 + 8;
#pragma unroll
        for (int nt = 0; nt < 4; nt++) {
            int cc = wn * 32 + nt * 8 + 2 * tg;
            if (r0 < NNODE)
                *(float2*)&outp[(size_t)r0 * FF + cc] =
                    make_float2(acc[mt][nt][0] * i0, acc[mt][nt][1] * i0);
            if (r1 < NNODE)
                *(float2*)&outp[(size_t)r1 * FF + cc] =
                    make_float2(acc[mt][nt][2] * i1, acc[mt][nt][3] * i1);
        }
    }

    // head 0: recompute + write normalized Sc (coalesced per warp-row)
    if (head == 0) {
        for (int k0 = 0; k0 < 320; k0 += 32) {
            int gc = k0 + c;
            if (gc >= NNODE) continue;
            float edc = ed[gc];
#pragma unroll
            for (int s = 0; s < 16; s++) {
                int r = rb0 + 4 * s;
                int gr = m0 + r;
                if (gr >= NNODE) continue;
                float val = 0.f;
                float a = adj[(size_t)gr * NNODE + gc];
                if (a > 0.f) {
                    float v = ess[r] + edc;
                    v = v > 0.f ? v : 0.3f * v;
                    val = __expf(v);
                }
                Sc[((size_t)bt * NNODE + gr) * NNODE + gc] = val * rinv[r];
            }
        }
    }
}

// ---------------- combine gates + transpose to [b,c,n,t]; also f1 --------
__global__ void k_combine(const float* __restrict__ t1w) {
    __shared__ float s[TT * 65];
    int b = blockIdx.x / NNODE;
    int n = blockIdx.x % NNODE;
    int tid = threadIdx.x;
    for (int i = tid; i < TT * FF; i += 256) {
        int t = i >> 6, c = i & 63;
        size_t off = ((size_t)(b * TT + t) * NNODE + n) * FF + c;
        float v1 = g_o1[off], v2 = g_o2[off];
        float filt = lrelu(v1, 0.01f);
        float gate = 1.f / (1.f + expf(-v2));
        s[t * 65 + c] = gate * filt;
    }
    __syncthreads();
    for (int i = tid; i < FF * TT; i += 256) {
        int c = i / TT, t = i % TT;
        g_x1g[((size_t)(b * FF + c) * NNODE + n) * TT + t] = s[t * 65 + c];
    }
    int warp = tid >> 5, lane = tid & 31;
    for (int t = warp; t < TT; t += 8) {
        float v = s[t * 65 + lane] * t1w[lane] + s[t * 65 + lane + 32] * t1w[lane + 32];
        for (int o = 16; o > 0; o >>= 1) v += __shfl_down_sync(0xffffffffu, v, o);
        if (lane == 0) g_f1[(size_t)(b * TT + t) * NNODE + n] = v;
    }
}

// ---------------- f2[b,c,t] = sum_n x1g * t2w[n] --------------------------
__global__ void k_f2(const float* __restrict__ t2w) {
    __shared__ float red[96];
    int bc = blockIdx.x;
    int tid = threadIdx.x;     // 96 threads
    int j = tid / TT, t = tid % TT;
    const float* xp = g_x1g + (size_t)bc * NNODE * TT;
    float s = 0.f;
    for (int n = j; n < NNODE; n += 4) s += xp[(size_t)n * TT + t] * t2w[n];
    red[tid] = s;
    __syncthreads();
    if (tid < TT) {
        float v = red[tid] + red[TT + tid] + red[2 * TT + tid] + red[3 * TT + tid];
        g_f2[(size_t)bc * TT + tid] = v;
    }
}

// ---------------- g[b,n,q] = sum_c tw[n,c]*f2[b,c,q] ---------------------
__global__ void k_g(const float* __restrict__ tw) {
    int idx = blockIdx.x * blockDim.x + threadIdx.x;
    if (idx >= BZ * NNODE * TT) return;
    int q = idx % TT;
    int n = (idx / TT) % NNODE;
    int b = idx / (TT * NNODE);
    float s = 0.f;
#pragma unroll 8
    for (int c = 0; c < FF; c++) s += tw[n * FF + c] * g_f2[(size_t)(b * FF + c) * TT + q];
    g_gm[idx] = s;
}

// ---------------- logits[b,t,q] = sigmoid(f1.g + tb) ----------------------
__global__ void k_logits(const float* __restrict__ tb) {
    __shared__ float f1s[NNODE];
    __shared__ float red[192];
    int bt = blockIdx.x;
    int b = bt / TT, t = bt % TT;
    int tid = threadIdx.x;     // 192 threads
    for (int i = tid; i < NNODE; i += 192) f1s[i] = g_f1[(size_t)bt * NNODE + i];
    __syncthreads();
    int j = tid / TT, q = tid % TT;
    const float* gp = g_gm + (size_t)b * NNODE * TT;
    float s = 0.f;
    for (int n = j; n < NNODE; n += 8) s += f1s[n] * gp[(size_t)n * TT + q];
    red[tid] = s;
    __syncthreads();
    if (tid < TT) {
        float v = tb[t * TT + tid];
#pragma unroll
        for (int jj = 0; jj < 8; jj++) v += red[jj * TT + tid];
        g_lg[(size_t)bt * TT + tid] = 1.f / (1.f + expf(-v));
    }
}

// ---------------- tv-mix + BN + causal softmax; write T_coef -------------
__global__ void k_coefs(const float* __restrict__ tv, const float* __restrict__ bn_g,
                        const float* __restrict__ bn_b, float* __restrict__ Tc) {
    __shared__ float s[TT * TT];
    int b = blockIdx.x;
    int tid = threadIdx.x;
    int p = tid / TT, q = tid % TT;
    float v = 0.f;
#pragma unroll
    for (int t = 0; t < TT; t++) v += tv[p * TT + t] * g_lg[(size_t)(b * TT + t) * TT + q];
    const float invs = rsqrtf(1.00001f);
    v = v * invs * bn_g[q] + bn_b[q];
    if (q > p) v += -1e13f;
    s[p * TT + q] = v;
    __syncthreads();
    if (tid < TT) {
        int pp = tid;
        float mx = -FLT_MAX;
        for (int j = 0; j < TT; j++) mx = fmaxf(mx, s[pp * TT + j]);
        float sum = 0.f;
        for (int j = 0; j < TT; j++) { float e = expf(s[pp * TT + j] - mx); s[pp * TT + j] = e; sum += e; }
        float inv = 1.f / sum;
        for (int j = 0; j < TT; j++) s[pp * TT + j] *= inv;
    }
    __syncthreads();
    Tc[(size_t)b * TT * TT + q * TT + p] = s[p * TT + q];
}

// ------- y = lrelu(x1 @ T_coef) + x_input(inline 1x1 conv); LN stats -----
__global__ void k_y(const float* __restrict__ Tc, const float* __restrict__ x,
                    const float* __restrict__ c1w, const float* __restrict__ c1b) {
    __shared__ __align__(8) float cs[TT * TT];
    __shared__ double rs[256];
    int b = blockIdx.y;
    int tid = threadIdx.x;
    for (int i = tid; i < TT * TT; i += 256) cs[i] = Tc[(size_t)b * TT * TT + i];
    __syncthreads();
    int r = blockIdx.x * 256 + tid;
    double s1 = 0.0, s2 = 0.0;
    if (r < FF * NNODE) {
        int c = r / NNODE, n = r % NNODE;
        size_t base = ((size_t)b * FF * NNODE + r) * TT;
        float xr[TT];
#pragma unroll
        for (int l = 0; l < TT; l++) xr[l] = g_x1g[base + l];
        ull acc[12];
#pragma unroll
        for (int qp = 0; qp < 12; qp++) acc[qp] = 0ull;
#pragma unroll
        for (int l = 0; l < TT; l++) {
            ull xd = pk2(xr[l], xr[l]);
#pragma unroll
            for (int qp = 0; qp < 12; qp++) {
                ull cv = *(const ull*)&cs[l * TT + 2 * qp];
                acc[qp] = fma2(xd, cv, acc[qp]);
            }
        }
        float w0 = c1w[c * CIN], w1 = c1w[c * CIN + 1], w2 = c1w[c * CIN + 2];
        float bb = c1b[c];
        const float* xb = x + ((size_t)(b * CIN) * NNODE + n) * TT;
        float xi[TT];
#pragma unroll
        for (int l = 0; l < TT; l++)
            xi[l] = bb + w0 * xb[l] + w1 * xb[NNODE * TT + l] + w2 * xb[2 * NNODE * TT + l];
#pragma unroll
        for (int qp = 0; qp < 12; qp++) {
            float2 v = upk2(acc[qp]);
            float y0 = lrelu(v.x, 0.01f) + xi[2 * qp];
            float y1 = lrelu(v.y, 0.01f) + xi[2 * qp + 1];
            g_y[base + 2 * qp] = y0;
            g_y[base + 2 * qp + 1] = y1;
            s1 += (double)y0 + (double)y1;
            s2 += (double)y0 * y0 + (double)y1 * y1;
        }
    }
    rs[tid] = s1; __syncthreads();
    for (int s = 128; s > 0; s >>= 1) { if (tid < s) rs[tid] += rs[tid + s]; __syncthreads(); }
    if (tid == 0) g_part[((size_t)b * 80 + blockIdx.x) * 2] = rs[0];
    __syncthreads();
    rs[tid] = s2; __syncthreads();
    for (int s = 128; s > 0; s >>= 1) { if (tid < s) rs[tid] += rs[tid + s]; __syncthreads(); }
    if (tid == 0) g_part[((size_t)b * 80 + blockIdx.x) * 2 + 1] = rs[0];
}

// ---------------- reduce stats -------------------------------------------
__global__ void k_stats() {
    int b = threadIdx.x;
    if (b >= BZ) return;
    double s1 = 0.0, s2 = 0.0;
    for (int j = 0; j < 77; j++) {
        s1 += g_part[((size_t)b * 80 + j) * 2];
        s2 += g_part[((size_t)b * 80 + j) * 2 + 1];
    }
    double mu = s1 / (double)PERB;
    double var = s2 / (double)PERB - mu * mu;
    g_mu[b] = (float)mu;
    g_rstd[b] = (float)(1.0 / sqrt(var + 1e-5));
}

// ---------------- final LayerNorm ----------------------------------------
__global__ void k_norm(const float* __restrict__ ln_w, const float* __restrict__ ln_b,
                       float* __restrict__ out) {
    int idx = blockIdx.x * blockDim.x + threadIdx.x;
    if (idx >= ELEMS) return;
    int b = idx / PERB;
    int r = idx % PERB;
    out[idx] = (g_y[idx] - g_mu[b]) * g_rstd[b] * ln_w[r] + ln_b[r];
}

extern "C" void kernel_launch(void* const* d_in, const int* in_sizes, int n_in,
                              void* d_out, int out_size) {
    const float* x       = (const float*)d_in[0];
    const float* supports= (const float*)d_in[1];
    const float* conv1_w = (const float*)d_in[2];
    const float* conv1_b = (const float*)d_in[3];
    const float* time_w  = (const float*)d_in[4];
    const float* time_b  = (const float*)d_in[5];
    const float* W1      = (const float*)d_in[6];
    const float* a1s     = (const float*)d_in[7];
    const float* a1d     = (const float*)d_in[8];
    const float* W2      = (const float*)d_in[9];
    const float* a2s     = (const float*)d_in[10];
    const float* a2d     = (const float*)d_in[11];
    const float* t1w     = (const float*)d_in[12];
    const float* t2w     = (const float*)d_in[13];
    const float* tw      = (const float*)d_in[14];
    const float* tb      = (const float*)d_in[15];
    const float* tv      = (const float*)d_in[16];
    const float* bn_g    = (const float*)d_in[17];
    const float* bn_b    = (const float*)d_in[18];
    const float* ln_w    = (const float*)d_in[19];
    const float* ln_b    = (const float*)d_in[20];

    float* out = (float*)d_out;
    float* Sc = out + (long long)ELEMS;
    float* Tc = out + (long long)ELEMS + S_SIZE;

    const int KH_SMEM = (64 * 68 + 64 * 136) * 4;     // 52224
    cudaFuncSetAttribute(k_hmma, cudaFuncAttributeMaxDynamicSharedMemorySize, KH_SMEM);

    int nb = (ELEMS + 255) / 256;
    k_tconv<<<nb, 256>>>(x, time_w, time_b);
    k_wa<<<1, 64>>>(W1, a1s, a1d, W2, a2s, a2d);
    k_esed<<<(BTN + 7) / 8, 256>>>();
    dim3 hg(5, BT);
    k_hmma<<<hg, 128, KH_SMEM>>>(W1, W2);     // profiled slot (#4)
    dim3 agg(5, BT, 2);
    k_fagg<<<agg, 128>>>(supports, Sc);
    k_combine<<<BZ * NNODE, 256>>>(t1w);
    k_f2<<<BZ * FF, 96>>>(t2w);
    k_g<<<(BZ * NNODE * TT + 255) / 256, 256>>>(tw);
    k_logits<<<BT, 192>>>(tb);
    k_coefs<<<BZ, TT * TT>>>(tv, bn_g, bn_b, Tc);
    dim3 yg(77, BZ);
    k_y<<<yg, 256>>>(Tc, x, conv1_w, conv1_b);
    k_stats<<<1, 32>>>();
    k_norm<<<nb, 256>>>(ln_w, ln_b, out);
}

// round 15
// speedup vs baseline: 1.6946x; 1.6946x over previous
#include <cuda_runtime.h>
#include <math.h>
#include <float.h>

#define BZ 16
#define CIN 3
#define FF 64
#define NNODE 307
#define TT 24
#define KT 3
#define BT (BZ*TT)               /* 384 */
#define BTN (BT*NNODE)           /* 117888 */
#define ELEMS (BZ*FF*NNODE*TT)   /* 7544832 */
#define PERB (FF*NNODE*TT)       /* 471552 */
#define S_SIZE ((long long)BT*NNODE*NNODE)  /* 36191616 */

typedef unsigned long long ull;
__device__ __forceinline__ ull pk2(float lo, float hi) {
    ull r; asm("mov.b64 %0, {%1,%2};" : "=l"(r) : "f"(lo), "f"(hi)); return r;
}
__device__ __forceinline__ ull fma2(ull a, ull b, ull c) {
    ull d; asm("fma.rn.f32x2 %0, %1, %2, %3;" : "=l"(d) : "l"(a), "l"(b), "l"(c)); return d;
}
__device__ __forceinline__ float2 upk2(ull v) {
    float2 r; asm("mov.b64 {%0,%1}, %2;" : "=f"(r.x), "=f"(r.y) : "l"(v)); return r;
}
__device__ __forceinline__ unsigned cvt_tf32(float f) {
    unsigned u; asm("cvt.rna.tf32.f32 %0, %1;" : "=r"(u) : "f"(f)); return u;
}

// ---------------- scratch ----------------
__device__ float g_x1a[ELEMS];    // lrelu(temporal conv) [b,n,t,c]
__device__ float g_h1[ELEMS];     // h for GAT1 [b,t,n,f]
__device__ float g_h2[ELEMS];     // h for GAT2 [b,t,n,f]
__device__ float g_o1[ELEMS];     // GAT1 out [b,t,n,f]
__device__ float g_o2[ELEMS];     // GAT2 out [b,t,n,f]
__device__ float g_x1g[ELEMS];    // sigmoid(gate)*lrelu(filt) [b,c,n,t]
__device__ float g_y[ELEMS];      // pre-LN [b,c,n,t]
__device__ float g_att2[S_SIZE];  // head-2 attention
__device__ float g_es1[BTN], g_ed1[BTN], g_es2[BTN], g_ed2[BTN];
__device__ float g_wa[4*FF];
__device__ float g_f1[BTN];           // [b,t,n]
__device__ float g_f2[BZ*FF*TT];      // [b,c,t]
__device__ float g_gm[BZ*NNODE*TT];   // [b,n,q]
__device__ float g_lg[BZ*TT*TT];      // [b,t,q]
__device__ double g_part[16*80*2];
__device__ float g_mu[BZ], g_rstd[BZ];

__device__ __forceinline__ float lrelu(float v, float s) { return v > 0.f ? v : s * v; }

// ---------------- temporal conv (1,3), pad (0,1), lrelu(0.01) ------------
__global__ void k_tconv(const float* __restrict__ x, const float* __restrict__ w,
                        const float* __restrict__ bias) {
    int idx = blockIdx.x * blockDim.x + threadIdx.x;  // [b,n,t,o], o fastest
    if (idx >= ELEMS) return;
    int o = idx % FF;
    int t = (idx / FF) % TT;
    int n = (idx / (FF * TT)) % NNODE;
    int b = idx / (FF * TT * NNODE);
    float s = bias[o];
#pragma unroll
    for (int c = 0; c < CIN; c++) {
#pragma unroll
        for (int k = 0; k < KT; k++) {
            int tt = t - 1 + k;
            if (tt >= 0 && tt < TT)
                s += x[((size_t)(b * CIN + c) * NNODE + n) * TT + tt] * w[(o * CIN + c) * KT + k];
        }
    }
    g_x1a[idx] = lrelu(s, 0.01f);
}

// ---------------- wa[c] = sum_f W[c,f]*a[f] ------------------------------
__global__ void k_wa(const float* __restrict__ W1, const float* __restrict__ a1s,
                     const float* __restrict__ a1d, const float* __restrict__ W2,
                     const float* __restrict__ a2s, const float* __restrict__ a2d) {
    int c = threadIdx.x;
    float s0 = 0.f, s1 = 0.f, s2 = 0.f, s3 = 0.f;
    for (int f = 0; f < FF; f++) {
        float w1 = W1[c * FF + f], w2 = W2[c * FF + f];
        s0 += w1 * a1s[f]; s1 += w1 * a1d[f];
        s2 += w2 * a2s[f]; s3 += w2 * a2d[f];
    }
    g_wa[c] = s0; g_wa[FF + c] = s1; g_wa[2 * FF + c] = s2; g_wa[3 * FF + c] = s3;
}

// ---------------- es/ed = x1a . wa  (warp per row) -----------------------
__global__ void k_esed() {
    int row = blockIdx.x * 8 + (threadIdx.x >> 5);
    if (row >= BTN) return;
    int lane = threadIdx.x & 31;
    int n = row % NNODE;
    int bt = row / NNODE;
    int b = bt / TT, t = bt % TT;
    const float* xr = g_x1a + ((size_t)(b * NNODE + n) * TT + t) * FF;
    float x0 = xr[lane], x1 = xr[lane + 32];
    float s0 = x0 * g_wa[lane]        + x1 * g_wa[lane + 32];
    float s1 = x0 * g_wa[FF + lane]   + x1 * g_wa[FF + lane + 32];
    float s2 = x0 * g_wa[2*FF + lane] + x1 * g_wa[2*FF + lane + 32];
    float s3 = x0 * g_wa[3*FF + lane] + x1 * g_wa[3*FF + lane + 32];
#pragma unroll
    for (int o = 16; o > 0; o >>= 1) {
        s0 += __shfl_xor_sync(0xffffffffu, s0, o);
        s1 += __shfl_xor_sync(0xffffffffu, s1, o);
        s2 += __shfl_xor_sync(0xffffffffu, s2, o);
        s3 += __shfl_xor_sync(0xffffffffu, s3, o);
    }
    if (lane == 0) { g_es1[row] = s0; g_ed1[row] = s1; g_es2[row] = s2; g_ed2[row] = s3; }
}

// ---------------- h1|h2 = x1a @ [W1|W2]  (tf32 MMA, N=128) ----------------
// grid (5, BT), block 128. dyn smem: As[64][68] + Ws[64][136] (tf32 bits)
extern __shared__ unsigned dyn_smem[];
__global__ void k_hmma(const float* __restrict__ W1, const float* __restrict__ W2) {
    unsigned (*As)[68] = (unsigned(*)[68])dyn_smem;
    unsigned (*Ws)[136] = (unsigned(*)[136])(dyn_smem + 64 * 68);
    int bt = blockIdx.y;
    int b = bt / TT, t = bt % TT;
    int m0 = blockIdx.x * 64;
    int tid = threadIdx.x, wid = tid >> 5, lane = tid & 31;
    int g = lane >> 2, tg = lane & 3;
    int wm = wid >> 1, wn = wid & 1;

    for (int i = tid; i < 4096; i += 128) {
        int r = i >> 6, c = i & 63;
        int n = m0 + r;
        float v = (n < NNODE) ? g_x1a[((size_t)(b * NNODE + n) * TT + t) * FF + c] : 0.f;
        As[r][c] = cvt_tf32(v);
    }
    for (int i = tid; i < 8192; i += 128) {
        int k = i >> 7, f = i & 127;
        float v = (f < 64) ? W1[k * FF + f] : W2[k * FF + (f - 64)];
        Ws[k][f] = cvt_tf32(v);
    }
    __syncthreads();

    float acc[2][8][4];
#pragma unroll
    for (int mt = 0; mt < 2; mt++)
#pragma unroll
        for (int nt = 0; nt < 8; nt++)
#pragma unroll
            for (int r = 0; r < 4; r++) acc[mt][nt][r] = 0.f;

#pragma unroll
    for (int k8 = 0; k8 < 64; k8 += 8) {
        unsigned a[2][4], bfr[8][2];
#pragma unroll
        for (int mt = 0; mt < 2; mt++) {
            int rb = wm * 32 + mt * 16 + g;
            a[mt][0] = As[rb][k8 + tg];
            a[mt][1] = As[rb + 8][k8 + tg];
            a[mt][2] = As[rb][k8 + tg + 4];
            a[mt][3] = As[rb + 8][k8 + tg + 4];
        }
#pragma unroll
        for (int nt = 0; nt < 8; nt++) {
            int cb = wn * 64 + nt * 8 + g;
            bfr[nt][0] = Ws[k8 + tg][cb];
            bfr[nt][1] = Ws[k8 + tg + 4][cb];
        }
#pragma unroll
        for (int mt = 0; mt < 2; mt++)
#pragma unroll
            for (int nt = 0; nt < 8; nt++)
                asm volatile(
                    "mma.sync.aligned.m16n8k8.row.col.f32.tf32.tf32.f32 "
                    "{%0,%1,%2,%3}, {%4,%5,%6,%7}, {%8,%9}, {%0,%1,%2,%3};"
                    : "+f"(acc[mt][nt][0]), "+f"(acc[mt][nt][1]),
                      "+f"(acc[mt][nt][2]), "+f"(acc[mt][nt][3])
                    : "r"(a[mt][0]), "r"(a[mt][1]), "r"(a[mt][2]), "r"(a[mt][3]),
                      "r"(bfr[nt][0]), "r"(bfr[nt][1]));
    }
#pragma unroll
    for (int mt = 0; mt < 2; mt++) {
        int l0 = wm * 32 + mt * 16 + g;
        int n0v = m0 + l0, n1v = n0v + 8;
#pragma unroll
        for (int nt = 0; nt < 8; nt++) {
            int c = wn * 64 + nt * 8 + 2 * tg;
            float* dst = (c < 64) ? g_h1 : g_h2;
            int cc = c & 63;
            if (n0v < NNODE)
                *(float2*)&dst[((size_t)bt * NNODE + n0v) * FF + cc] = make_float2(acc[mt][nt][0], acc[mt][nt][1]);
            if (n1v < NNODE)
                *(float2*)&dst[((size_t)bt * NNODE + n1v) * FF + cc] = make_float2(acc[mt][nt][2], acc[mt][nt][3]);
        }
    }
}

// ---------------- masked softmax for both heads (warp per row) ------------
__global__ void k_soft(const float* __restrict__ adj, float* __restrict__ Sc) {
    int bt = blockIdx.y;
    int row = blockIdx.x * 8 + (threadIdx.x >> 5);
    if (row >= NNODE) return;
    int lane = threadIdx.x & 31;
    float es1v = g_es1[(size_t)bt * NNODE + row];
    float es2v = g_es2[(size_t)bt * NNODE + row];
    const float* ed1 = g_ed1 + (size_t)bt * NNODE;
    const float* ed2 = g_ed2 + (size_t)bt * NNODE;
    const float* adjp = adj + (size_t)row * NNODE;
    float e1[10], e2[10];
    float mx1 = -FLT_MAX, mx2 = -FLT_MAX;
#pragma unroll
    for (int j = 0; j < 10; j++) {
        int m = lane + 32 * j;
        float v1 = -9e15f, v2 = -9e15f;
        if (m < NNODE) {
            float a = adjp[m];
            if (a > 0.f) {
                v1 = es1v + ed1[m]; v1 = v1 > 0.f ? v1 : 0.3f * v1;
                v2 = es2v + ed2[m]; v2 = v2 > 0.f ? v2 : 0.3f * v2;
            }
        }
        e1[j] = v1; e2[j] = v2;
        mx1 = fmaxf(mx1, v1); mx2 = fmaxf(mx2, v2);
    }
#pragma unroll
    for (int o = 16; o > 0; o >>= 1) {
        mx1 = fmaxf(mx1, __shfl_xor_sync(0xffffffffu, mx1, o));
        mx2 = fmaxf(mx2, __shfl_xor_sync(0xffffffffu, mx2, o));
    }
    float s1 = 0.f, s2 = 0.f;
#pragma unroll
    for (int j = 0; j < 10; j++) {
        int m = lane + 32 * j;
        float x1 = (m < NNODE) ? __expf(e1[j] - mx1) : 0.f;
        float x2 = (m < NNODE) ? __expf(e2[j] - mx2) : 0.f;
        e1[j] = x1; e2[j] = x2;
        s1 += x1; s2 += x2;
    }
#pragma unroll
    for (int o = 16; o > 0; o >>= 1) {
        s1 += __shfl_xor_sync(0xffffffffu, s1, o);
        s2 += __shfl_xor_sync(0xffffffffu, s2, o);
    }
    float i1 = 1.f / s1, i2 = 1.f / s2;
    float* scp = Sc + ((size_t)bt * NNODE + row) * NNODE;
    float* a2p = g_att2 + ((size_t)bt * NNODE + row) * NNODE;
#pragma unroll
    for (int j = 0; j < 10; j++) {
        int m = lane + 32 * j;
        if (m < NNODE) {
            scp[m] = e1[j] * i1;
            a2p[m] = e2[j] * i2;
        }
    }
}

// ---------------- tf32 tensor-core aggregation: out = att @ h -------------
// grid (5, BT, 2), block 128 (4 warps). BM=BN=64, BK=32.
// R8 skeleton; single change: software-pipelined fills (LDG of chunk k+1
// issued before MMA of chunk k; cvt+STS after the MMA barrier).
__global__ void k_agg(const float* __restrict__ Sc) {
    __shared__ unsigned As[64][36];
    __shared__ unsigned Bs[32][68];
    int bt = blockIdx.y;
    int head = blockIdx.z;
    int m0 = blockIdx.x * 64;
    const float* A = (head ? g_att2 : Sc) + (size_t)bt * NNODE * NNODE;
    const float* B = (head ? g_h2 : g_h1) + (size_t)bt * NNODE * FF;
    float* outp = (head ? g_o2 : g_o1) + (size_t)bt * NNODE * FF;
    int tid = threadIdx.x, wid = tid >> 5, lane = tid & 31;
    int g = lane >> 2, tg = lane & 3;
    int wm = wid >> 1, wn = wid & 1;
    float acc[2][4][4];
#pragma unroll
    for (int mt = 0; mt < 2; mt++)
#pragma unroll
        for (int nt = 0; nt < 4; nt++)
#pragma unroll
            for (int r = 0; r < 4; r++) acc[mt][nt][r] = 0.f;

    float ra[16], rb[16];
    // prologue: load chunk 0 into registers
#pragma unroll
    for (int j = 0; j < 16; j++) {
        int i = tid + 128 * j;
        int gr = m0 + (i >> 5), gc = i & 31;
        ra[j] = (gr < NNODE && gc < NNODE) ? A[(size_t)gr * NNODE + gc] : 0.f;
    }
#pragma unroll
    for (int j = 0; j < 16; j++) {
        int i = tid + 128 * j;
        int gk = i >> 6, c = i & 63;
        rb[j] = (gk < NNODE) ? B[(size_t)gk * FF + c] : 0.f;
    }
#pragma unroll
    for (int j = 0; j < 16; j++) {
        int i = tid + 128 * j;
        As[i >> 5][i & 31] = cvt_tf32(ra[j]);
        Bs[i >> 6][i & 63] = cvt_tf32(rb[j]);
    }
    __syncthreads();

    for (int k0 = 0; k0 < 320; k0 += 32) {
        int kn = k0 + 32;
        bool more = (kn < 320);
        // prefetch next chunk into registers (LDG in flight during MMA)
        if (more) {
#pragma unroll
            for (int j = 0; j < 16; j++) {
                int i = tid + 128 * j;
                int gr = m0 + (i >> 5), gc = kn + (i & 31);
                ra[j] = (gr < NNODE && gc < NNODE) ? A[(size_t)gr * NNODE + gc] : 0.f;
            }
#pragma unroll
            for (int j = 0; j < 16; j++) {
                int i = tid + 128 * j;
                int gk = kn + (i >> 6), c = i & 63;
                rb[j] = (gk < NNODE) ? B[(size_t)gk * FF + c] : 0.f;
            }
        }
        // MMA on current smem tiles
#pragma unroll
        for (int k8 = 0; k8 < 32; k8 += 8) {
            unsigned a[2][4], b[4][2];
#pragma unroll
            for (int mt = 0; mt < 2; mt++) {
                int rbq = wm * 32 + mt * 16 + g;
                a[mt][0] = As[rbq][k8 + tg];
                a[mt][1] = As[rbq + 8][k8 + tg];
                a[mt][2] = As[rbq][k8 + tg + 4];
                a[mt][3] = As[rbq + 8][k8 + tg + 4];
            }
#pragma unroll
            for (int nt = 0; nt < 4; nt++) {
                int cb = wn * 32 + nt * 8 + g;
                b[nt][0] = Bs[k8 + tg][cb];
                b[nt][1] = Bs[k8 + tg + 4][cb];
            }
#pragma unroll
            for (int mt = 0; mt < 2; mt++)
#pragma unroll
                for (int nt = 0; nt < 4; nt++)
                    asm volatile(
                        "mma.sync.aligned.m16n8k8.row.col.f32.tf32.tf32.f32 "
                        "{%0,%1,%2,%3}, {%4,%5,%6,%7}, {%8,%9}, {%0,%1,%2,%3};"
                        : "+f"(acc[mt][nt][0]), "+f"(acc[mt][nt][1]),
                          "+f"(acc[mt][nt][2]), "+f"(acc[mt][nt][3])
                        : "r"(a[mt][0]), "r"(a[mt][1]), "r"(a[mt][2]), "r"(a[mt][3]),
                          "r"(b[nt][0]), "r"(b[nt][1]));
        }
        __syncthreads();
        if (more) {
#pragma unroll
            for (int j = 0; j < 16; j++) {
                int i = tid + 128 * j;
                As[i >> 5][i & 31] = cvt_tf32(ra[j]);
                Bs[i >> 6][i & 63] = cvt_tf32(rb[j]);
            }
        }
        __syncthreads();
    }
#pragma unroll
    for (int mt = 0; mt < 2; mt++) {
        int r0 = m0 + wm * 32 + mt * 16 + g;
        int r1 = r0 + 8;
#pragma unroll
        for (int nt = 0; nt < 4; nt++) {
            int c = wn * 32 + nt * 8 + 2 * tg;
            if (r0 < NNODE)
                *(float2*)&outp[(size_t)r0 * FF + c] = make_float2(acc[mt][nt][0], acc[mt][nt][1]);
            if (r1 < NNODE)
                *(float2*)&outp[(size_t)r1 * FF + c] = make_float2(acc[mt][nt][2], acc[mt][nt][3]);
        }
    }
}

// ---------------- combine gates + transpose to [b,c,n,t]; also f1 --------
__global__ void k_combine(const float* __restrict__ t1w) {
    __shared__ float s[TT * 65];
    int b = blockIdx.x / NNODE;
    int n = blockIdx.x % NNODE;
    int tid = threadIdx.x;
    for (int i = tid; i < TT * FF; i += 256) {
        int t = i >> 6, c = i & 63;
        size_t off = ((size_t)(b * TT + t) * NNODE + n) * FF + c;
        float v1 = g_o1[off], v2 = g_o2[off];
        float filt = lrelu(v1, 0.01f);
        float gate = 1.f / (1.f + expf(-v2));
        s[t * 65 + c] = gate * filt;
    }
    __syncthreads();
    for (int i = tid; i < FF * TT; i += 256) {
        int c = i / TT, t = i % TT;
        g_x1g[((size_t)(b * FF + c) * NNODE + n) * TT + t] = s[t * 65 + c];
    }
    int warp = tid >> 5, lane = tid & 31;
    for (int t = warp; t < TT; t += 8) {
        float v = s[t * 65 + lane] * t1w[lane] + s[t * 65 + lane + 32] * t1w[lane + 32];
        for (int o = 16; o > 0; o >>= 1) v += __shfl_down_sync(0xffffffffu, v, o);
        if (lane == 0) g_f1[(size_t)(b * TT + t) * NNODE + n] = v;
    }
}

// ---------------- f2[b,c,t] = sum_n x1g * t2w[n] --------------------------
__global__ void k_f2(const float* __restrict__ t2w) {
    __shared__ float red[96];
    int bc = blockIdx.x;
    int tid = threadIdx.x;     // 96 threads
    int j = tid / TT, t = tid % TT;
    const float* xp = g_x1g + (size_t)bc * NNODE * TT;
    float s = 0.f;
    for (int n = j; n < NNODE; n += 4) s += xp[(size_t)n * TT + t] * t2w[n];
    red[tid] = s;
    __syncthreads();
    if (tid < TT) {
        float v = red[tid] + red[TT + tid] + red[2 * TT + tid] + red[3 * TT + tid];
        g_f2[(size_t)bc * TT + tid] = v;
    }
}

// ---------------- g[b,n,q] = sum_c tw[n,c]*f2[b,c,q] ---------------------
__global__ void k_g(const float* __restrict__ tw) {
    int idx = blockIdx.x * blockDim.x + threadIdx.x;
    if (idx >= BZ * NNODE * TT) return;
    int q = idx % TT;
    int n = (idx / TT) % NNODE;
    int b = idx / (TT * NNODE);
    float s = 0.f;
#pragma unroll 8
    for (int c = 0; c < FF; c++) s += tw[n * FF + c] * g_f2[(size_t)(b * FF + c) * TT + q];
    g_gm[idx] = s;
}

// ---------------- logits[b,t,q] = sigmoid(f1.g + tb) ----------------------
__global__ void k_logits(const float* __restrict__ tb) {
    __shared__ float f1s[NNODE];
    __shared__ float red[192];
    int bt = blockIdx.x;
    int b = bt / TT, t = bt % TT;
    int tid = threadIdx.x;     // 192 threads
    for (int i = tid; i < NNODE; i += 192) f1s[i] = g_f1[(size_t)bt * NNODE + i];
    __syncthreads();
    int j = tid / TT, q = tid % TT;
    const float* gp = g_gm + (size_t)b * NNODE * TT;
    float s = 0.f;
    for (int n = j; n < NNODE; n += 8) s += f1s[n] * gp[(size_t)n * TT + q];
    red[tid] = s;
    __syncthreads();
    if (tid < TT) {
        float v = tb[t * TT + tid];
#pragma unroll
        for (int jj = 0; jj < 8; jj++) v += red[jj * TT + tid];
        g_lg[(size_t)bt * TT + tid] = 1.f / (1.f + expf(-v));
    }
}

// ---------------- tv-mix + BN + causal softmax; write T_coef -------------
__global__ void k_coefs(const float* __restrict__ tv, const float* __restrict__ bn_g,
                        const float* __restrict__ bn_b, float* __restrict__ Tc) {
    __shared__ float s[TT * TT];
    int b = blockIdx.x;
    int tid = threadIdx.x;
    int p = tid / TT, q = tid % TT;
    float v = 0.f;
#pragma unroll
    for (int t = 0; t < TT; t++) v += tv[p * TT + t] * g_lg[(size_t)(b * TT + t) * TT + q];
    const float invs = rsqrtf(1.00001f);
    v = v * invs * bn_g[q] + bn_b[q];
    if (q > p) v += -1e13f;
    s[p * TT + q] = v;
    __syncthreads();
    if (tid < TT) {
        int pp = tid;
        float mx = -FLT_MAX;
        for (int j = 0; j < TT; j++) mx = fmaxf(mx, s[pp * TT + j]);
        float sum = 0.f;
        for (int j = 0; j < TT; j++) { float e = expf(s[pp * TT + j] - mx); s[pp * TT + j] = e; sum += e; }
        float inv = 1.f / sum;
        for (int j = 0; j < TT; j++) s[pp * TT + j] *= inv;
    }
    __syncthreads();
    Tc[(size_t)b * TT * TT + q * TT + p] = s[p * TT + q];
}

// ------- y = lrelu(x1 @ T_coef) + x_input(inline 1x1 conv); LN stats -----
__global__ void k_y(const float* __restrict__ Tc, const float* __restrict__ x,
                    const float* __restrict__ c1w, const float* __restrict__ c1b) {
    __shared__ __align__(8) float cs[TT * TT];
    __shared__ double rs[256];
    int b = blockIdx.y;
    int tid = threadIdx.x;
    for (int i = tid; i < TT * TT; i += 256) cs[i] = Tc[(size_t)b * TT * TT + i];
    __syncthreads();
    int r = blockIdx.x * 256 + tid;
    double s1 = 0.0, s2 = 0.0;
    if (r < FF * NNODE) {
        int c = r / NNODE, n = r % NNODE;
        size_t base = ((size_t)b * FF * NNODE + r) * TT;
        float xr[TT];
#pragma unroll
        for (int l = 0; l < TT; l++) xr[l] = g_x1g[base + l];
        ull acc[12];
#pragma unroll
        for (int qp = 0; qp < 12; qp++) acc[qp] = 0ull;
#pragma unroll
        for (int l = 0; l < TT; l++) {
            ull xd = pk2(xr[l], xr[l]);
#pragma unroll
            for (int qp = 0; qp < 12; qp++) {
                ull cv = *(const ull*)&cs[l * TT + 2 * qp];
                acc[qp] = fma2(xd, cv, acc[qp]);
            }
        }
        float w0 = c1w[c * CIN], w1 = c1w[c * CIN + 1], w2 = c1w[c * CIN + 2];
        float bb = c1b[c];
        const float* xb = x + ((size_t)(b * CIN) * NNODE + n) * TT;
        float xi[TT];
#pragma unroll
        for (int l = 0; l < TT; l++)
            xi[l] = bb + w0 * xb[l] + w1 * xb[NNODE * TT + l] + w2 * xb[2 * NNODE * TT + l];
#pragma unroll
        for (int qp = 0; qp < 12; qp++) {
            float2 v = upk2(acc[qp]);
            float y0 = lrelu(v.x, 0.01f) + xi[2 * qp];
            float y1 = lrelu(v.y, 0.01f) + xi[2 * qp + 1];
            g_y[base + 2 * qp] = y0;
            g_y[base + 2 * qp + 1] = y1;
            s1 += (double)y0 + (double)y1;
            s2 += (double)y0 * y0 + (double)y1 * y1;
        }
    }
    rs[tid] = s1; __syncthreads();
    for (int s = 128; s > 0; s >>= 1) { if (tid < s) rs[tid] += rs[tid + s]; __syncthreads(); }
    if (tid == 0) g_part[((size_t)b * 80 + blockIdx.x) * 2] = rs[0];
    __syncthreads();
    rs[tid] = s2; __syncthreads();
    for (int s = 128; s > 0; s >>= 1) { if (tid < s) rs[tid] += rs[tid + s]; __syncthreads(); }
    if (tid == 0) g_part[((size_t)b * 80 + blockIdx.x) * 2 + 1] = rs[0];
}

// ---------------- reduce stats -------------------------------------------
__global__ void k_stats() {
    int b = threadIdx.x;
    if (b >= BZ) return;
    double s1 = 0.0, s2 = 0.0;
    for (int j = 0; j < 77; j++) {
        s1 += g_part[((size_t)b * 80 + j) * 2];
        s2 += g_part[((size_t)b * 80 + j) * 2 + 1];
    }
    double mu = s1 / (double)PERB;
    double var = s2 / (double)PERB - mu * mu;
    g_mu[b] = (float)mu;
    g_rstd[b] = (float)(1.0 / sqrt(var + 1e-5));
}

// ---------------- final LayerNorm ----------------------------------------
__global__ void k_norm(const float* __restrict__ ln_w, const float* __restrict__ ln_b,
                       float* __restrict__ out) {
    int idx = blockIdx.x * blockDim.x + threadIdx.x;
    if (idx >= ELEMS) return;
    int b = idx / PERB;
    int r = idx % PERB;
    out[idx] = (g_y[idx] - g_mu[b]) * g_rstd[b] * ln_w[r] + ln_b[r];
}

extern "C" void kernel_launch(void* const* d_in, const int* in_sizes, int n_in,
                              void* d_out, int out_size) {
    const float* x       = (const float*)d_in[0];
    const float* supports= (const float*)d_in[1];
    const float* conv1_w = (const float*)d_in[2];
    const float* conv1_b = (const float*)d_in[3];
    const float* time_w  = (const float*)d_in[4];
    const float* time_b  = (const float*)d_in[5];
    const float* W1      = (const float*)d_in[6];
    const float* a1s     = (const float*)d_in[7];
    const float* a1d     = (const float*)d_in[8];
    const float* W2      = (const float*)d_in[9];
    const float* a2s     = (const float*)d_in[10];
    const float* a2d     = (const float*)d_in[11];
    const float* t1w     = (const float*)d_in[12];
    const float* t2w     = (const float*)d_in[13];
    const float* tw      = (const float*)d_in[14];
    const float* tb      = (const float*)d_in[15];
    const float* tv      = (const float*)d_in[16];
    const float* bn_g    = (const float*)d_in[17];
    const float* bn_b    = (const float*)d_in[18];
    const float* ln_w    = (const float*)d_in[19];
    const float* ln_b    = (const float*)d_in[20];

    float* out = (float*)d_out;
    float* Sc = out + (long long)ELEMS;
    float* Tc = out + (long long)ELEMS + S_SIZE;

    const int KH_SMEM = (64 * 68 + 64 * 136) * 4;     // 52224
    cudaFuncSetAttribute(k_hmma, cudaFuncAttributeMaxDynamicSharedMemorySize, KH_SMEM);

    int nb = (ELEMS + 255) / 256;
    k_tconv<<<nb, 256>>>(x, time_w, time_b);
    k_wa<<<1, 64>>>(W1, a1s, a1d, W2, a2s, a2d);
    k_esed<<<(BTN + 7) / 8, 256>>>();
    dim3 hg(5, BT);
    k_hmma<<<hg, 128, KH_SMEM>>>(W1, W2);     // profiled slot (#4)
    dim3 sg((NNODE + 7) / 8, BT);
    k_soft<<<sg, 256>>>(supports, Sc);
    dim3 agg(5, BT, 2);
    k_agg<<<agg, 128>>>(Sc);
    k_combine<<<BZ * NNODE, 256>>>(t1w);
    k_f2<<<BZ * FF, 96>>>(t2w);
    k_g<<<(BZ * NNODE * TT + 255) / 256, 256>>>(tw);
    k_logits<<<BT, 192>>>(tb);
    k_coefs<<<BZ, TT * TT>>>(tv, bn_g, bn_b, Tc);
    dim3 yg(77, BZ);
    k_y<<<yg, 256>>>(Tc, x, conv1_w, conv1_b);
    k_stats<<<1, 32>>>();
    k_norm<<<nb, 256>>>(ln_w, ln_b, out);
}